// round 1
// baseline (speedup 1.0000x reference)
#include <cuda_runtime.h>
#include <cstdint>

// Problem constants (fixed by the dataset)
#define KMAX 24   // max n-grams per word
#define EV4  32   // E=128 floats = 32 float4 per row

// word_idx:      [B*S]      int32
// ngram_ids:     [V, 24]    int32   (slot >= count padded with 0; id 0 == zero row)
// ngram_counts:  [V]        int32
// emb_table:     [NG, 128]  float32
// out:           [B*S, 128] float32  = mean over valid ngram embeddings
__global__ __launch_bounds__(256, 8)
void ngram_emb_kernel(const int* __restrict__ word_idx,
                      const int* __restrict__ ngram_ids,
                      const int* __restrict__ ngram_counts,
                      const float4* __restrict__ emb,   // viewed as [NG, 32] float4
                      float4* __restrict__ out,         // viewed as [B*S, 32] float4
                      int n_words) {
    const int warp = (blockIdx.x * blockDim.x + threadIdx.x) >> 5;
    const int lane = threadIdx.x & 31;
    if (warp >= n_words) return;

    const int w = __ldg(&word_idx[warp]);

    // Lanes 0..23 fetch the 24 ngram ids for this word (coalesced 96B read).
    int id_l = 0;
    if (lane < KMAX) id_l = __ldg(&ngram_ids[w * KMAX + lane]);
    const int cnt = __ldg(&ngram_counts[w]);

    // 4 independent accumulators to break the FADD dependency chain and let
    // ptxas front-batch the predicated LDG.128s (high MLP).
    float4 a0 = make_float4(0.f, 0.f, 0.f, 0.f);
    float4 a1 = make_float4(0.f, 0.f, 0.f, 0.f);
    float4 a2 = make_float4(0.f, 0.f, 0.f, 0.f);
    float4 a3 = make_float4(0.f, 0.f, 0.f, 0.f);

    #pragma unroll
    for (int k = 0; k < KMAX; k += 4) {
        const int i0 = __shfl_sync(0xffffffffu, id_l, k + 0);
        const int i1 = __shfl_sync(0xffffffffu, id_l, k + 1);
        const int i2 = __shfl_sync(0xffffffffu, id_l, k + 2);
        const int i3 = __shfl_sync(0xffffffffu, id_l, k + 3);
        // id 0 is the padding row -> contributes zero; skip the load entirely.
        if (i0) { float4 v = __ldg(&emb[(size_t)i0 * EV4 + lane]);
                  a0.x += v.x; a0.y += v.y; a0.z += v.z; a0.w += v.w; }
        if (i1) { float4 v = __ldg(&emb[(size_t)i1 * EV4 + lane]);
                  a1.x += v.x; a1.y += v.y; a1.z += v.z; a1.w += v.w; }
        if (i2) { float4 v = __ldg(&emb[(size_t)i2 * EV4 + lane]);
                  a2.x += v.x; a2.y += v.y; a2.z += v.z; a2.w += v.w; }
        if (i3) { float4 v = __ldg(&emb[(size_t)i3 * EV4 + lane]);
                  a3.x += v.x; a3.y += v.y; a3.z += v.z; a3.w += v.w; }
    }

    const float inv = 1.0f / (float)cnt;
    float4 r;
    r.x = (a0.x + a1.x + a2.x + a3.x) * inv;
    r.y = (a0.y + a1.y + a2.y + a3.y) * inv;
    r.z = (a0.z + a1.z + a2.z + a3.z) * inv;
    r.w = (a0.w + a1.w + a2.w + a3.w) * inv;
    out[(size_t)warp * EV4 + lane] = r;
}

extern "C" void kernel_launch(void* const* d_in, const int* in_sizes, int n_in,
                              void* d_out, int out_size) {
    const int*   word_idx     = (const int*)d_in[0];   // [B*S]
    const int*   ngram_ids    = (const int*)d_in[1];   // [V*24]
    const int*   ngram_counts = (const int*)d_in[2];   // [V]
    const float* emb_table    = (const float*)d_in[3]; // [NG*128]
    float*       out          = (float*)d_out;

    const int n_words = in_sizes[0];                   // 32768
    const int threads = 256;                           // 8 warps / block
    const int warps_per_block = threads / 32;
    const int blocks = (n_words + warps_per_block - 1) / warps_per_block;

    ngram_emb_kernel<<<blocks, threads>>>(word_idx, ngram_ids, ngram_counts,
                                          (const float4*)emb_table,
                                          (float4*)out, n_words);
}